// round 14
// baseline (speedup 1.0000x reference)
#include <cuda_runtime.h>
#include <cstdint>

// Focal CTC loss — bidirectional split scan, 4 steps/barrier, with:
//  * exp-preconverted emission ring: conv warps 4-7 (one per SMSP) own private
//    cp.async pipelines (raw stage -> ex2 -> exp ring, one interval ahead), so
//    compute-side emissions are plain LDS (no redundant ex2).
//  * linear-domain state across intervals: smem pair state = (valU,valV,exp)
//    float4; neighbor reconcile via ex2f(e_i - e_max) power-of-2 scales
//    (R12/R13-validated window truncation); renorm = exponent extraction.
// grid = 2B (dir = bid&1, b = bid>>1), block = 256 (warps 0-3 compute,
// warps 4-7 convert). Second finisher per sample combines
// ll = LSE_s(alpha_Tm + beta_Tm) + focal weights; final scalar factorizes.

#define CFIX  256
#define NEG2  (-1e30f)
#define DEADE (-1e9f)
#define LOG2E 1.4426950408889634f
#define LN2   0.6931471805599453f

__device__ float    g_mid[64][2][128][2];
__device__ float    g_tps[64][2][128];
__device__ unsigned g_done[64];
__device__ float    g_loss[64];
__device__ float    g_wsum[64];
__device__ unsigned g_ctr = 0;

__device__ __forceinline__ float ex2f(float x){ float y; asm("ex2.approx.ftz.f32 %0,%1;":"=f"(y):"f"(x)); return y; }
__device__ __forceinline__ float lg2f(float x){ float y; asm("lg2.approx.ftz.f32 %0,%1;":"=f"(y):"f"(x)); return y; }

__device__ __forceinline__ float lse2p(float a, float b, float e) {
    float hi = fmaxf(a, b), lo = fminf(a, b);
    return fmaf(e, LOG2E, hi + lg2f(1.0f + ex2f(lo - hi)));
}
__device__ __forceinline__ float lse3p(float a, float b, float c, float e) {
    float hi = fmaxf(a, b), lo = fminf(a, b);
    float m  = fmaxf(hi, c), o1 = fminf(hi, c);
    return fmaf(e, LOG2E, m + lg2f(1.0f + ex2f(o1 - m) + ex2f(lo - m)));
}
__device__ __forceinline__ float lse2(float a, float b) {
    float hi = fmaxf(a, b), lo = fminf(a, b);
    return hi + lg2f(1.0f + ex2f(lo - hi));
}
__device__ __forceinline__ float lse3(float a, float b, float c) {
    float hi = fmaxf(a, b), lo = fminf(a, b);
    float m  = fmaxf(hi, c), o1 = fminf(hi, c);
    return m + lg2f(1.0f + ex2f(o1 - m) + ex2f(lo - m));
}
__device__ __forceinline__ float toLog(float v, float e) {
    return (v > 0.0f) ? (lg2f(v) + e) : NEG2;
}

__device__ __forceinline__ void finalize(float* out, int B, int L)
{
    __threadfence();
    unsigned v = atomicAdd(&g_ctr, 1u);
    if (v == (unsigned)(B - 1)) {
        g_ctr = 0;
        __threadfence();
        float ls = 0.0f, ws = 0.0f;
        for (int i = 0; i < B; i++) {
            ls += __ldcg(&g_loss[i]);
            ws += __ldcg(&g_wsum[i]);
        }
        out[0] = (ls / (float)B) * (ws / ((float)B * (float)L));
    }
}

__global__ __launch_bounds__(256, 1)
void focal_ctc_kernel(const float* __restrict__ lp,      // (T,B,C)
                      const int*   __restrict__ targets, // (B*L)
                      const int*   __restrict__ in_len,  // (B)
                      const int*   __restrict__ tg_len,  // (B)
                      float*       __restrict__ out,
                      int T, int B, int L)
{
    __shared__ __align__(16) float  rawS[4][4][CFIX];   // per-conv-warp raw stage (16 KB)
    __shared__ __align__(16) float  expR[8][CFIX];      // exp emission ring (8 KB)
    __shared__ __align__(16) float4 ab4[2][132];        // pair state (valU,valV,exp,_)
    __shared__ float redm[4], reds[4], redww[4];
    __shared__ unsigned sflag;

    const int tid = threadIdx.x, w = tid >> 5, lane = tid & 31;
    const int bid = blockIdx.x;
    const int dir = bid & 1, b = bid >> 1;
    const int len = in_len[b], tl = tg_len[b];
    const int bL  = b * L;
    const int Tm  = len >> 1;
    const int nB  = len - 1 - Tm;
    const size_t tstr = (size_t)B * CFIX;
    const float* rowb = lp + (size_t)b * CFIX;

    // pads (both layouts): dead pairs
    if (tid < 4) { ab4[0][tid] = make_float4(0,0,DEADE,0); ab4[1][tid] = make_float4(0,0,DEADE,0); }
    if (tid >= 128 && tid < 132) { ab4[0][tid] = make_float4(0,0,DEADE,0); ab4[1][tid] = make_float4(0,0,DEADE,0); }

    const int j  = tid;              // pair index (compute warps)
    const int cv = w - 4;            // conv warp index (conv warps)
    const bool cw = (w < 4);
    const bool hasU = cw && (j <= L);
    const bool hasV = cw && (j <= L - 1);

    float vU = 0.f, vV = 0.f, eS = DEADE, acc = 0.0f;

    #define CONV_ISSUE(SLOT, ROW)                                                   \
    {                                                                               \
        const float* s_ = rowb + (size_t)(ROW) * tstr + lane * 8;                   \
        uint32_t d_ = (uint32_t)__cvta_generic_to_shared(&rawS[cv][SLOT][lane*8]);  \
        asm volatile("cp.async.ca.shared.global [%0], [%1], 16;" :: "r"(d_),      "l"(s_)     : "memory"); \
        asm volatile("cp.async.ca.shared.global [%0], [%1], 16;" :: "r"(d_ + 16), "l"(s_ + 4) : "memory"); \
    }
    #define CONV_DO(SLOT, Q)                                                        \
    {                                                                               \
        float4 a_ = *(const float4*)&rawS[cv][SLOT][lane*8];                        \
        float4 b_ = *(const float4*)&rawS[cv][SLOT][lane*8 + 4];                    \
        float4 ea_, eb_;                                                            \
        ea_.x = ex2f(a_.x*LOG2E); ea_.y = ex2f(a_.y*LOG2E);                         \
        ea_.z = ex2f(a_.z*LOG2E); ea_.w = ex2f(a_.w*LOG2E);                         \
        eb_.x = ex2f(b_.x*LOG2E); eb_.y = ex2f(b_.y*LOG2E);                         \
        eb_.z = ex2f(b_.z*LOG2E); eb_.w = ex2f(b_.w*LOG2E);                         \
        *(float4*)&expR[(Q) & 7][lane*8]     = ea_;                                 \
        *(float4*)&expR[(Q) & 7][lane*8 + 4] = eb_;                                 \
    }

    if (dir == 0) {
        // ======================= FORWARD =======================
        int c0 = 0, c1 = 0, c2 = 0, c3 = 0, c4f = 0;
        float af0 = 0.f, af1 = 0.f, af2 = 0.f, af3 = 0.f;
        if (cw) {
            if (j     < L) c0  = targets[bL + j];
            if (j >= 1 && j - 1 < L) c1 = targets[bL + j - 1];
            if (j >= 2 && j - 2 < L) c2 = targets[bL + j - 2];
            if (j >= 3 && j - 3 < L) c3 = targets[bL + j - 3];
            if (j >= 4 && j - 4 < L) c4f = targets[bL + j - 4];
            af0 = (j >= 1 && j     < L && c0 != c1)  ? 1.f : 0.f;
            af1 = (j >= 2 && j - 1 < L && c1 != c2)  ? 1.f : 0.f;
            af2 = (j >= 3 && j - 2 < L && c2 != c3)  ? 1.f : 0.f;
            af3 = (j >= 4 && j - 3 < L && c3 != c4f) ? 1.f : 0.f;
        }
        const int nI = (Tm >= 4) ? ((Tm - 4) >> 2) + 1 : 0;   // intervals t = 1+4i, t+3 <= Tm

        // ---- prologue ----
        if (!cw) {
            #pragma unroll
            for (int g = 0; g < 3; g++) {
                int q = 1 + cv + 4 * g;
                if (q <= Tm) CONV_ISSUE(g, q)
                asm volatile("cp.async.commit_group;" ::: "memory");
            }
            asm volatile("cp.async.wait_group 2;" ::: "memory");
            { int q = 1 + cv; if (q <= Tm) CONV_DO(0, q) }
        } else {
            // t = 0 init (direct global)
            float lc = __ldcg(rowb + c0);
            acc = ex2f(lc * LOG2E);
            if (j == 0) {
                float xU = __ldcg(rowb) * LOG2E;
                float xV = lc * LOG2E;
                eS = floorf(fmaxf(xU, xV));
                vU = ex2f(xU - eS);
                vV = ex2f(xV - eS);
            }
            ab4[0][4 + j] = make_float4(vU, vV, eS, 0);
        }

        int rb = 0;
        for (int i = 0; i < nI; i++) {
            __syncthreads();
            if (!cw) {
                int g = 3 + i;
                int q = 1 + cv + 4 * g;
                if (q <= Tm) CONV_ISSUE(g & 3, q)
                asm volatile("cp.async.commit_group;" ::: "memory");
                asm volatile("cp.async.wait_group 2;" ::: "memory");
                int gc = i + 1;
                int qc = 1 + cv + 4 * gc;
                if (qc <= Tm) CONV_DO(gc & 3, qc)
            } else {
                const int t = 1 + 4 * i;
                float4 n1 = ab4[rb][3 + j], n2 = ab4[rb][2 + j];
                float4 n3 = ab4[rb][1 + j], n4 = ab4[rb][j];
                // exponent reconcile
                float me = fmaxf(fmaxf(eS, n1.z), fmaxf(fmaxf(n2.z, n3.z), n4.z));
                float s0 = ex2f(eS - me),  s1 = ex2f(n1.z - me);
                float s2 = ex2f(n2.z - me), s3 = ex2f(n3.z - me), s4 = ex2f(n4.z - me);
                float U0 = vU * s0,   V0 = vV * s0;
                float U1 = n1.x * s1, V1 = n1.y * s1;
                float U2 = n2.x * s2, V2 = n2.y * s2;
                float U3 = n3.x * s3, V3 = n3.y * s3;
                float V4 = n4.y * s4;
                // emissions from exp ring (linear probs)
                const float* E0 = &expR[(t    ) & 7][0];
                const float* E1 = &expR[(t + 1) & 7][0];
                const float* E2 = &expR[(t + 2) & 7][0];
                const float* E3 = &expR[(t + 3) & 7][0];
                float pB0 = E0[0], pB1 = E1[0], pB2 = E2[0], pB3 = E3[0];
                float pA00 = E0[c0], pA01 = E0[c1], pA02 = E0[c2], pA03 = E0[c3];
                float pA10 = E1[c0], pA11 = E1[c1], pA12 = E1[c2];
                float pA20 = E2[c0], pA21 = E2[c1];
                float pA30 = E3[c0];
                acc += pA00 + pA10 + pA20 + pA30;
                // 4-step pyramid (R13 math)
                float tU0 = (U0 + V1) * pB0, tV0 = fmaf(af0, V1, V0 + U0) * pA00;
                float tU1 = (U1 + V2) * pB0, tV1 = fmaf(af1, V2, V1 + U1) * pA01;
                float tU2 = (U2 + V3) * pB0, tV2 = fmaf(af2, V3, V2 + U2) * pA02;
                float tU3 = (U3 + V4) * pB0, tV3 = fmaf(af3, V4, V3 + U3) * pA03;
                float sU0 = (tU0 + tV1) * pB1, sV0 = fmaf(af0, tV1, tV0 + tU0) * pA10;
                float sU1 = (tU1 + tV2) * pB1, sV1 = fmaf(af1, tV2, tV1 + tU1) * pA11;
                float sU2 = (tU2 + tV3) * pB1, sV2 = fmaf(af2, tV3, tV2 + tU2) * pA12;
                float rU0 = (sU0 + sV1) * pB2, rV0 = fmaf(af0, sV1, sV0 + sU0) * pA20;
                float rU1 = (sU1 + sV2) * pB2, rV1 = fmaf(af1, sV2, sV1 + sU1) * pA21;
                float qU = (rU0 + rV1) * pB3,  qV = fmaf(af0, rV1, rV0 + rU0) * pA30;
                qU = hasU ? qU : 0.f;
                qV = hasV ? qV : 0.f;
                float mm = fmaxf(qU, qV);
                if (mm > 0.f) {
                    int ex = (int)(__float_as_uint(mm) >> 23) - 127;
                    float scl = __uint_as_float((unsigned)(127 - ex) << 23);
                    vU = qU * scl; vV = qV * scl; eS = me + (float)ex;
                } else { vU = 0.f; vV = 0.f; eS = DEADE; }
                ab4[rb ^ 1][4 + j] = make_float4(vU, vV, eS, 0);
            }
            rb ^= 1;
        }
        // ---- tail (<=3 single steps, log domain, direct global) ----
        const int tT = 1 + 4 * nI;
        float teB[3], teV[3];
        if (cw) {
            #pragma unroll
            for (int q = 0; q < 3; q++) {
                int t = tT + q;
                if (t <= Tm) {
                    teB[q] = __ldcg(rowb + (size_t)t * tstr);
                    teV[q] = __ldcg(rowb + (size_t)t * tstr + c0);
                }
            }
        }
        if (!cw) { asm volatile("cp.async.wait_group 0;" ::: "memory"); }
        #pragma unroll
        for (int q = 0; q < 3; q++) {
            int t = tT + q;
            if (t <= Tm) {
                __syncthreads();
                if (cw) {
                    float4 n1 = ab4[rb][3 + j];
                    float xU = toLog(vU, eS), xV = toLog(vV, eS);
                    float xVm = toLog(n1.y, n1.z);
                    float nU = lse2p(xU, xVm, teB[q]);
                    float nV = lse3p(xV, xU, (af0 > 0.5f) ? xVm : NEG2, teV[q]);
                    acc += ex2f(teV[q] * LOG2E);
                    nU = hasU ? nU : NEG2;
                    nV = hasV ? nV : NEG2;
                    float mx = fmaxf(nU, nV);
                    if (mx > -1e29f) {
                        float eI = floorf(mx);
                        vU = ex2f(nU - eI); vV = ex2f(nV - eI); eS = eI;
                    } else { vU = 0.f; vV = 0.f; eS = DEADE; }
                    ab4[rb ^ 1][4 + j] = make_float4(vU, vV, eS, 0);
                }
                rb ^= 1;
            }
        }
    } else {
        // ======================= BACKWARD =======================
        int c0 = 0, c1 = 0, c2 = 0, c3 = 0, c4 = 0;
        float aN0 = 0.f, aN1 = 0.f, aN2 = 0.f, aN3 = 0.f;
        if (cw) {
            if (j     < L) c0 = targets[bL + j];
            if (j + 1 < L) c1 = targets[bL + j + 1];
            if (j + 2 < L) c2 = targets[bL + j + 2];
            if (j + 3 < L) c3 = targets[bL + j + 3];
            if (j + 4 < L) c4 = targets[bL + j + 4];
            aN0 = (j + 1 < L && c1 != c0) ? 1.f : 0.f;
            aN1 = (j + 2 < L && c2 != c1) ? 1.f : 0.f;
            aN2 = (j + 3 < L && c3 != c2) ? 1.f : 0.f;
            aN3 = (j + 4 < L && c4 != c3) ? 1.f : 0.f;
        }
        const int nI = (nB >= 4) ? ((nB - 4) >> 2) + 1 : 0;   // intervals k = 4i, k+3 <= nB-1

        if (!cw) {
            #pragma unroll
            for (int g = 0; g < 3; g++) {
                int q = cv + 4 * g;
                if (q < nB) CONV_ISSUE(g, len - 1 - q)
                asm volatile("cp.async.commit_group;" ::: "memory");
            }
            asm volatile("cp.async.wait_group 2;" ::: "memory");
            { int q = cv; if (q < nB) CONV_DO(0, q) }
        } else {
            vU = (j == tl)     ? 1.f : 0.f;
            vV = (j == tl - 1) ? 1.f : 0.f;
            eS = (vU > 0.f || vV > 0.f) ? 0.f : DEADE;
            ab4[0][j] = make_float4(vU, vV, eS, 0);
        }

        int rb = 0;
        for (int i = 0; i < nI; i++) {
            __syncthreads();
            if (!cw) {
                int g = 3 + i;
                int q = cv + 4 * g;
                if (q < nB) CONV_ISSUE(g & 3, len - 1 - q)
                asm volatile("cp.async.commit_group;" ::: "memory");
                asm volatile("cp.async.wait_group 2;" ::: "memory");
                int gc = i + 1;
                int qc = cv + 4 * gc;
                if (qc < nB) CONV_DO(gc & 3, qc)
            } else {
                const int k = 4 * i;
                float4 n1 = ab4[rb][j + 1], n2 = ab4[rb][j + 2];
                float4 n3 = ab4[rb][j + 3], n4 = ab4[rb][j + 4];
                float me = fmaxf(fmaxf(eS, n1.z), fmaxf(fmaxf(n2.z, n3.z), n4.z));
                float s0 = ex2f(eS - me),  s1 = ex2f(n1.z - me);
                float s2 = ex2f(n2.z - me), s3 = ex2f(n3.z - me), s4 = ex2f(n4.z - me);
                float U0 = vU * s0,   V0 = vV * s0;
                float U1 = n1.x * s1, V1 = n1.y * s1;
                float U2 = n2.x * s2, V2 = n2.y * s2;
                float U3 = n3.x * s3, V3 = n3.y * s3;
                float U4 = n4.x * s4, V4 = n4.y * s4;
                const float* E0 = &expR[(k    ) & 7][0];
                const float* E1 = &expR[(k + 1) & 7][0];
                const float* E2 = &expR[(k + 2) & 7][0];
                const float* E3 = &expR[(k + 3) & 7][0];
                float pB0 = E0[0], pB1 = E1[0], pB2 = E2[0], pB3 = E3[0];
                float pA00 = E0[c0], pA01 = E0[c1], pA02 = E0[c2], pA03 = E0[c3], pA04 = E0[c4];
                float pA10 = E1[c0], pA11 = E1[c1], pA12 = E1[c2], pA13 = E1[c3];
                float pA20 = E2[c0], pA21 = E2[c1], pA22 = E2[c2];
                float pA30 = E3[c0], pA31 = E3[c1];
                acc += pA00 + pA10 + pA20 + pA30;
                float w0 = V0 * pA00, w1 = V1 * pA01, w2 = V2 * pA02,
                      w3 = V3 * pA03, w4 = V4 * pA04;
                float tU0 = fmaf(U0, pB0, w0), tV0 = fmaf(aN0, w1, fmaf(U1, pB0, w0));
                float tU1 = fmaf(U1, pB0, w1), tV1 = fmaf(aN1, w2, fmaf(U2, pB0, w1));
                float tU2 = fmaf(U2, pB0, w2), tV2 = fmaf(aN2, w3, fmaf(U3, pB0, w2));
                float tU3 = fmaf(U3, pB0, w3), tV3 = fmaf(aN3, w4, fmaf(U4, pB0, w3));
                float x0 = tV0 * pA10, x1 = tV1 * pA11, x2 = tV2 * pA12, x3 = tV3 * pA13;
                float sU0 = fmaf(tU0, pB1, x0), sV0 = fmaf(aN0, x1, fmaf(tU1, pB1, x0));
                float sU1 = fmaf(tU1, pB1, x1), sV1 = fmaf(aN1, x2, fmaf(tU2, pB1, x1));
                float sU2 = fmaf(tU2, pB1, x2), sV2 = fmaf(aN2, x3, fmaf(tU3, pB1, x2));
                float y0 = sV0 * pA20, y1 = sV1 * pA21, y2 = sV2 * pA22;
                float rU0 = fmaf(sU0, pB2, y0), rV0 = fmaf(aN0, y1, fmaf(sU1, pB2, y0));
                float rU1 = fmaf(sU1, pB2, y1), rV1 = fmaf(aN1, y2, fmaf(sU2, pB2, y1));
                float z0 = rV0 * pA30, z1 = rV1 * pA31;
                float qU = fmaf(rU0, pB3, z0), qV = fmaf(aN0, z1, fmaf(rU1, pB3, z0));
                qU = hasU ? qU : 0.f;
                qV = hasV ? qV : 0.f;
                float mm = fmaxf(qU, qV);
                if (mm > 0.f) {
                    int ex = (int)(__float_as_uint(mm) >> 23) - 127;
                    float scl = __uint_as_float((unsigned)(127 - ex) << 23);
                    vU = qU * scl; vV = qV * scl; eS = me + (float)ex;
                } else { vU = 0.f; vV = 0.f; eS = DEADE; }
                ab4[rb ^ 1][j] = make_float4(vU, vV, eS, 0);
            }
            rb ^= 1;
        }
        // ---- tail (<=3 single steps, log domain, direct global) ----
        const int kT = 4 * nI;
        float teB[3], teA[3], teC[3];
        if (cw) {
            #pragma unroll
            for (int q = 0; q < 3; q++) {
                int k = kT + q;
                if (k <= nB - 1) {
                    const float* R = rowb + (size_t)(len - 1 - k) * tstr;
                    teB[q] = __ldcg(R); teA[q] = __ldcg(R + c0); teC[q] = __ldcg(R + c1);
                }
            }
        }
        if (!cw) { asm volatile("cp.async.wait_group 0;" ::: "memory"); }
        #pragma unroll
        for (int q = 0; q < 3; q++) {
            int k = kT + q;
            if (k <= nB - 1) {
                __syncthreads();
                if (cw) {
                    float4 n1 = ab4[rb][j + 1];
                    float xU = toLog(vU, eS), xV = toLog(vV, eS);
                    float xU1 = toLog(n1.x, n1.z), xV1 = toLog(n1.y, n1.z);
                    float eB = teB[q] * LOG2E, eA = teA[q] * LOG2E, eC = teC[q] * LOG2E;
                    acc += ex2f(eA);
                    float nU = lse2(xU + eB, xV + eA);
                    float nV = lse3(xV + eA, xU1 + eB, (aN0 > 0.5f) ? (xV1 + eC) : NEG2);
                    nU = hasU ? nU : NEG2;
                    nV = hasV ? nV : NEG2;
                    float mx = fmaxf(nU, nV);
                    if (mx > -1e29f) {
                        float eI = floorf(mx);
                        vU = ex2f(nU - eI); vV = ex2f(nV - eI); eS = eI;
                    } else { vU = 0.f; vV = 0.f; eS = DEADE; }
                    ab4[rb ^ 1][j] = make_float4(vU, vV, eS, 0);
                }
                rb ^= 1;
            }
        }
    }

    // ---- publish mid-state (log2) + tps partials ----
    if (cw) {
        g_mid[b][dir][j][0] = toLog(vU, eS);
        g_mid[b][dir][j][1] = toLog(vV, eS);
        g_tps[b][dir][j]    = acc;
    }
    __threadfence();
    __syncthreads();
    if (tid == 0) sflag = atomicAdd(&g_done[b], 1u);
    __syncthreads();

    if (sflag == 1) {                    // second finisher: combine this sample
        float cU = NEG2, cV = NEG2, mj = NEG2;
        if (cw) {
            float a0 = __ldcg(&g_mid[b][0][j][0]), a1 = __ldcg(&g_mid[b][0][j][1]);
            float b0 = __ldcg(&g_mid[b][1][j][0]), b1 = __ldcg(&g_mid[b][1][j][1]);
            cU = a0 + b0;  cV = a1 + b1;
            mj = fmaxf(cU, cV);
            #pragma unroll
            for (int o = 16; o; o >>= 1) mj = fmaxf(mj, __shfl_xor_sync(0xFFFFFFFFu, mj, o));
            if (lane == 0) redm[w] = mj;
        }
        __syncthreads();
        float M = fmaxf(fmaxf(redm[0], redm[1]), fmaxf(redm[2], redm[3]));
        float sj = 0.0f, wgt = 0.0f;
        if (cw) {
            sj = ex2f(cU - M) + ex2f(cV - M);
            if (j < L) {
                float tps = __ldcg(&g_tps[b][0][j]) + __ldcg(&g_tps[b][1][j]);
                float om  = 1.0f - tps * (1.0f / (float)T);
                wgt = om * om;                       // GAMMA = 2
            }
            #pragma unroll
            for (int o = 16; o; o >>= 1) {
                sj  += __shfl_xor_sync(0xFFFFFFFFu, sj, o);
                wgt += __shfl_xor_sync(0xFFFFFFFFu, wgt, o);
            }
            if (lane == 0) { reds[w] = sj; redww[w] = wgt; }
        }
        __syncthreads();
        if (tid == 0) {
            float ss = reds[0] + reds[1] + reds[2] + reds[3];
            float ll = (M + lg2f(ss)) * LN2;
            g_loss[b] = (ll > -5e29f) ? -ll : 0.0f;   // zero_infinity
            g_wsum[b] = redww[0] + redww[1] + redww[2] + redww[3];
            g_done[b] = 0;                            // reset for graph replay
            finalize(out, B, L);
        }
    }
    #undef CONV_ISSUE
    #undef CONV_DO
}

extern "C" void kernel_launch(void* const* d_in, const int* in_sizes, int n_in,
                              void* d_out, int out_size)
{
    const float* lp      = (const float*)d_in[0];
    const int*   targets = (const int*)d_in[1];
    const int*   in_len  = (const int*)d_in[2];
    const int*   tg_len  = (const int*)d_in[3];

    int B = in_sizes[2];                 // 64
    int L = in_sizes[1] / B;             // 100
    int T = in_sizes[0] / (B * CFIX);    // 1000

    focal_ctc_kernel<<<2 * B, 256>>>(lp, targets, in_len, tg_len, (float*)d_out, T, B, L);
}